// round 5
// baseline (speedup 1.0000x reference)
#include <cuda_runtime.h>
#include <cuda_bf16.h>
#include <stdint.h>

#define N_NODES 50000
#define N_EDGES 800000
#define TPB 256

// ---------------- scratch (device globals; no allocation allowed) ----------
__device__ int   g_is64;
__device__ int   g_deg[N_NODES];
__device__ int   g_rowptr[N_NODES + 1];
__device__ int   g_rowcur[N_NODES];
__device__ int   g_colidx[N_EDGES];
__device__ int   g_bsum[2048];
__device__ float g_dis[N_NODES];
// write-once feature buffers (no rewrite => plain L1 loads are coherent)
__device__ float g_f16a[N_NODES * 16];   // dis*x
__device__ float g_f16b[N_NODES * 16];   // agg16 out
__device__ float g_f32 [N_NODES * 32];   // conv1 out (dis-scaled)
__device__ float g_a32 [N_NODES * 32];   // agg32 out
__device__ float g_f64 [N_NODES * 64];   // conv2 out (dis-scaled)
__device__ float g_a64 [N_NODES * 64];   // agg64 out
__device__ float g_h128[N_NODES * 128];  // conv3 out
__device__ float g_h64 [N_NODES * 64];   // dense l1 out
__device__ float g_h32 [N_NODES * 32];   // dense l2 out

// ---------------- grid-wide barrier -----------------------------------------
__device__ volatile unsigned g_gen;
__device__ unsigned g_cnt;

__device__ __forceinline__ void grid_sync() {
    __syncthreads();
    if (threadIdx.x == 0) {
        unsigned target = g_gen + 1u;
        __threadfence();
        if (atomicAdd(&g_cnt, 1u) == gridDim.x - 1u) {
            atomicExch(&g_cnt, 0u);
            __threadfence();
            atomicExch((unsigned*)&g_gen, target);
        } else {
            while (g_gen != target) __nanosleep(64);
        }
        __threadfence();
    }
    __syncthreads();
}

// ---------------- packed f32x2 helpers (Blackwell) ---------------------------
__device__ __forceinline__ unsigned long long pack2(float x, float y) {
    unsigned long long r;
    asm("mov.b64 %0, {%1, %2};" : "=l"(r) : "f"(x), "f"(y));
    return r;
}
__device__ __forceinline__ void unpack2(unsigned long long v, float& x, float& y) {
    asm("mov.b64 {%0, %1}, %2;" : "=f"(x), "=f"(y) : "l"(v));
}
__device__ __forceinline__ unsigned long long fma2(unsigned long long a,
                                                   unsigned long long b,
                                                   unsigned long long c) {
    unsigned long long d;
    asm("fma.rn.f32x2 %0, %1, %2, %3;" : "=l"(d) : "l"(a), "l"(b), "l"(c));
    return d;
}

__device__ __forceinline__ int edge_at(const void* ei, int is64, long long idx) {
    if (is64) return (int)((const long long*)ei)[idx];
    return ((const int*)ei)[idx];
}

// ---------------- block exclusive scan (256 threads) --------------------------
__device__ __forceinline__ int block_excl_scan(int v, int* ws, int& total) {
    int tid = threadIdx.x, lane = tid & 31, w = tid >> 5;
    int incl = v;
#pragma unroll
    for (int off = 1; off < 32; off <<= 1) {
        int t = __shfl_up_sync(0xffffffffu, incl, off);
        if (lane >= off) incl += t;
    }
    if (lane == 31) ws[w] = incl;
    __syncthreads();
    if (tid == 0) {
        int r = 0;
#pragma unroll
        for (int j = 0; j < 8; j++) { int t = ws[j]; ws[j] = r; r += t; }
        ws[8] = r;
    }
    __syncthreads();
    total = ws[8];
    int e = incl - v + ws[w];
    __syncthreads();
    return e;
}

// ---------------- aggregation phases -----------------------------------------
__device__ void agg16_phase(const float* __restrict__ G, float* __restrict__ A) {
    int half = blockIdx.x * (TPB / 16) + (threadIdx.x >> 4);
    int stride = gridDim.x * (TPB / 16);
    int lane = threadIdx.x & 15;
    for (int n = half; n < N_NODES; n += stride) {
        float acc = __ldg(&G[n * 16 + lane]);
        int p   = __ldcg(&g_rowptr[n]);
        int end = __ldcg(&g_rowptr[n + 1]);
        for (; p + 2 <= end; p += 2) {
            int s0 = __ldcg(&g_colidx[p]);
            int s1 = __ldcg(&g_colidx[p + 1]);
            acc += __ldg(&G[s0 * 16 + lane]);
            acc += __ldg(&G[s1 * 16 + lane]);
        }
        if (p < end) acc += __ldg(&G[__ldcg(&g_colidx[p]) * 16 + lane]);
        A[n * 16 + lane] = acc * g_dis[n];
    }
}

__device__ void agg32_phase(const float* __restrict__ G, float* __restrict__ A) {
    int warp = blockIdx.x * (TPB / 32) + (threadIdx.x >> 5);
    int stride = gridDim.x * (TPB / 32);
    int lane = threadIdx.x & 31;
    for (int n = warp; n < N_NODES; n += stride) {
        float acc = __ldg(&G[(size_t)n * 32 + lane]);
        int p   = __ldcg(&g_rowptr[n]);
        int end = __ldcg(&g_rowptr[n + 1]);
        for (; p + 4 <= end; p += 4) {
            int s0 = __ldcg(&g_colidx[p]),     s1 = __ldcg(&g_colidx[p + 1]);
            int s2 = __ldcg(&g_colidx[p + 2]), s3 = __ldcg(&g_colidx[p + 3]);
            acc += __ldg(&G[(size_t)s0 * 32 + lane]);
            acc += __ldg(&G[(size_t)s1 * 32 + lane]);
            acc += __ldg(&G[(size_t)s2 * 32 + lane]);
            acc += __ldg(&G[(size_t)s3 * 32 + lane]);
        }
        for (; p < end; p++)
            acc += __ldg(&G[(size_t)__ldcg(&g_colidx[p]) * 32 + lane]);
        A[(size_t)n * 32 + lane] = acc * g_dis[n];
    }
}

__device__ void agg64_phase(const float* __restrict__ G, float* __restrict__ A) {
    int warp = blockIdx.x * (TPB / 32) + (threadIdx.x >> 5);
    int stride = gridDim.x * (TPB / 32);
    int lane = threadIdx.x & 31;
    const float2* G2 = (const float2*)G;
    for (int n = warp; n < N_NODES; n += stride) {
        float2 acc = __ldg(&G2[(size_t)n * 32 + lane]);
        int p   = __ldcg(&g_rowptr[n]);
        int end = __ldcg(&g_rowptr[n + 1]);
        for (; p + 4 <= end; p += 4) {
            int s0 = __ldcg(&g_colidx[p]),     s1 = __ldcg(&g_colidx[p + 1]);
            int s2 = __ldcg(&g_colidx[p + 2]), s3 = __ldcg(&g_colidx[p + 3]);
            float2 v0 = __ldg(&G2[(size_t)s0 * 32 + lane]);
            float2 v1 = __ldg(&G2[(size_t)s1 * 32 + lane]);
            float2 v2 = __ldg(&G2[(size_t)s2 * 32 + lane]);
            float2 v3 = __ldg(&G2[(size_t)s3 * 32 + lane]);
            acc.x += v0.x + v1.x + v2.x + v3.x;
            acc.y += v0.y + v1.y + v2.y + v3.y;
        }
        for (; p < end; p++) {
            float2 v = __ldg(&G2[(size_t)__ldcg(&g_colidx[p]) * 32 + lane]);
            acc.x += v.x; acc.y += v.y;
        }
        float dd = g_dis[n];
        float2 o; o.x = acc.x * dd; o.y = acc.y * dd;
        ((float2*)A)[(size_t)n * 32 + lane] = o;
    }
}

// ---------------- GEMM phase: out = relu(in @ W + b) * (SCOUT ? dis : 1) ----
template <int DIN, int DOUT, int NB, bool SCOUT>
__device__ void gemm_phase(const float* __restrict__ in,
                           const float* __restrict__ W,
                           const float* __restrict__ b,
                           float* __restrict__ out,
                           float* smem) {
    constexpr int TN  = (DOUT >= 32) ? 8 : 4;
    constexpr int TX  = DOUT / TN;
    constexpr int TY  = TPB / TX;
    constexpr int TM  = NB / TY;
    static_assert(TM >= 1, "bad tiling");
    constexpr int KC  = (DIN * DOUT >= 8192) ? 32 : DIN;
    constexpr int NKC = DIN / KC;
    constexpr int INP = KC + 1;
    constexpr int SWW = DOUT + 2 * (DOUT / 32) + 2;

    float* inS = smem;
    float* Ws  = smem + NB * INP;

    const int tid = threadIdx.x;
    const int tx  = tid % TX;
    const int ty  = tid / TX;

    float bb[TN];
#pragma unroll
    for (int j = 0; j < TN; j++) bb[j] = __ldg(&b[tx * TN + j]);

    const int nTiles = (N_NODES + NB - 1) / NB;
    for (int tile = blockIdx.x; tile < nTiles; tile += gridDim.x) {
        const int node0 = tile * NB;
        unsigned long long acc[TM][TN / 2];
#pragma unroll
        for (int m = 0; m < TM; m++)
#pragma unroll
            for (int j = 0; j < TN / 2; j++) acc[m][j] = 0ull;

        for (int kc = 0; kc < NKC; kc++) {
            const int k0 = kc * KC;
            __syncthreads();
            for (int i = tid; i < NB * KC; i += TPB) {
                int r = i / KC, c = i - r * KC;
                int node = node0 + r;
                inS[r * INP + c] =
                    (node < N_NODES) ? __ldg(&in[(size_t)node * DIN + k0 + c]) : 0.f;
            }
            for (int i = tid; i < KC * DOUT; i += TPB) {
                int r = i / DOUT, c = i - r * DOUT;
                Ws[r * SWW + c + 2 * (c >> 5)] = __ldg(&W[(size_t)(k0 + r) * DOUT + c]);
            }
            __syncthreads();

#pragma unroll
            for (int k = 0; k < KC; k++) {
                unsigned long long a2[TM];
#pragma unroll
                for (int m = 0; m < TM; m++) {
                    float a = inS[(ty * TM + m) * INP + k];
                    a2[m] = pack2(a, a);
                }
#pragma unroll
                for (int j = 0; j < TN / 2; j++) {
                    int c = tx * TN + 2 * j;
                    float2 wv = *reinterpret_cast<const float2*>(
                        &Ws[k * SWW + c + 2 * (c >> 5)]);
                    unsigned long long w2 = pack2(wv.x, wv.y);
#pragma unroll
                    for (int m = 0; m < TM; m++)
                        acc[m][j] = fma2(a2[m], w2, acc[m][j]);
                }
            }
        }

#pragma unroll
        for (int m = 0; m < TM; m++) {
            int node = node0 + ty * TM + m;
            if (node >= N_NODES) continue;
            float sc = SCOUT ? g_dis[node] : 1.f;
            float vals[TN];
#pragma unroll
            for (int j = 0; j < TN / 2; j++) {
                float v0, v1;
                unpack2(acc[m][j], v0, v1);
                v0 += bb[2 * j];     v1 += bb[2 * j + 1];
                v0 = v0 > 0.f ? v0 : 0.f;
                v1 = v1 > 0.f ? v1 : 0.f;
                vals[2 * j]     = v0 * sc;
                vals[2 * j + 1] = v1 * sc;
            }
            float4* o = (float4*)(out + (size_t)node * DOUT + tx * TN);
#pragma unroll
            for (int q = 0; q < TN / 4; q++)
                o[q] = make_float4(vals[4 * q], vals[4 * q + 1],
                                   vals[4 * q + 2], vals[4 * q + 3]);
        }
    }
}

// ---------------- the persistent kernel --------------------------------------
__global__ void __launch_bounds__(TPB) k_persist(
        const float* __restrict__ x, const void* __restrict__ ei,
        const float* __restrict__ W1,  const float* __restrict__ b1,
        const float* __restrict__ W2,  const float* __restrict__ b2,
        const float* __restrict__ W3,  const float* __restrict__ b3,
        const float* __restrict__ Wl1, const float* __restrict__ bl1,
        const float* __restrict__ Wl2, const float* __restrict__ bl2,
        const float* __restrict__ Wl3, const float* __restrict__ bl3,
        float* __restrict__ out) {
    __shared__ float s_mem[6528];
    int* wsi = (int*)s_mem;   // scan scratch (9 ints)

    const int tid     = threadIdx.x;
    const int gtid    = blockIdx.x * TPB + tid;
    const int gstride = gridDim.x * TPB;

    // ---- phase 0: zero degrees + dtype probe ----
    for (int i = gtid; i < N_NODES; i += gstride) g_deg[i] = 0;
    if (gtid == 0) {
        const long long* p = (const long long*)ei;
        int ok64 = 1;
        for (int q = 0; q < 64; q++) {
            long long v = p[q];
            if (v < 0 || v >= N_NODES) { ok64 = 0; break; }
        }
        g_is64 = ok64;
    }
    grid_sync();

    const int is64 = __ldcg(&g_is64);

    // ---- phase 1: degree histogram ----
    for (int e = gtid; e < N_EDGES; e += gstride) {
        int d = edge_at(ei, is64, (long long)N_EDGES + e);
        if (d >= 0 && d < N_NODES) atomicAdd(&g_deg[d], 1);
    }
    grid_sync();

    // ---- phase 2: per-block local scan ----
    const int chunk = (N_NODES + gridDim.x - 1) / gridDim.x;
    {
        int start = blockIdx.x * chunk;
        int end   = min(start + chunk, N_NODES);
        int running = 0;
        for (int base = start; base < end; base += TPB) {
            int i = base + tid;
            int v = (i < end) ? __ldcg(&g_deg[i]) : 0;
            int tot;
            int e = block_excl_scan(v, wsi, tot);
            if (i < end) g_rowptr[i] = running + e;
            running += tot;
        }
        if (tid == 0) g_bsum[blockIdx.x] = (start < end) ? running : 0;
    }
    grid_sync();

    // ---- phase 3: scan of block sums (block 0 only) ----
    if (blockIdx.x == 0) {
        int nb = gridDim.x;
        int running = 0;
        for (int base = 0; base < nb; base += TPB) {
            int j = base + tid;
            int v = (j < nb) ? __ldcg(&g_bsum[j]) : 0;
            int tot;
            int e = block_excl_scan(v, wsi, tot);
            if (j < nb) g_bsum[j] = e + running;
            running += tot;
        }
        if (tid == 0) g_rowptr[N_NODES] = running;
    }
    grid_sync();

    // ---- phase 4: finalize rowptr/rowcur/dis ----
    for (int i = gtid; i < N_NODES; i += gstride) {
        int r = __ldcg(&g_rowptr[i]) + __ldcg(&g_bsum[i / chunk]);
        g_rowptr[i] = r;
        g_rowcur[i] = r;
        g_dis[i]    = rsqrtf((float)(__ldcg(&g_deg[i]) + 1));
    }
    grid_sync();

    // ---- phase 5: scatter edges + scale layer-1 input ----
    for (int e = gtid; e < N_EDGES; e += gstride) {
        int s = edge_at(ei, is64, e);
        int d = edge_at(ei, is64, (long long)N_EDGES + e);
        if (d >= 0 && d < N_NODES && s >= 0 && s < N_NODES) {
            int p = atomicAdd(&g_rowcur[d], 1);
            g_colidx[p] = s;
        }
    }
    {
        const float4* x4 = (const float4*)x;
        float4* f4 = (float4*)g_f16a;
        for (int i = gtid; i < N_NODES * 4; i += gstride) {
            float d = g_dis[i >> 2];
            float4 v = __ldg(&x4[i]);
            v.x *= d; v.y *= d; v.z *= d; v.w *= d;
            f4[i] = v;
        }
    }
    grid_sync();

    // ---- conv 1: 16 -> 32 ----
    agg16_phase(g_f16a, g_f16b);
    grid_sync();
    gemm_phase<16, 32, 64, true>(g_f16b, W1, b1, g_f32, s_mem);
    grid_sync();

    // ---- conv 2: 32 -> 64 ----
    agg32_phase(g_f32, g_a32);
    grid_sync();
    gemm_phase<32, 64, 32, true>(g_a32, W2, b2, g_f64, s_mem);
    grid_sync();

    // ---- conv 3: 64 -> 128 ----
    agg64_phase(g_f64, g_a64);
    grid_sync();
    gemm_phase<64, 128, 32, false>(g_a64, W3, b3, g_h128, s_mem);
    grid_sync();

    // ---- dense layers ----
    gemm_phase<128, 64, 32, false>(g_h128, Wl1, bl1, g_h64, s_mem);
    grid_sync();
    gemm_phase<64, 32, 64, false>(g_h64, Wl2, bl2, g_h32, s_mem);
    grid_sync();
    gemm_phase<32, 16, 64, false>(g_h32, Wl3, bl3, out, s_mem);
}

// ---------------- launch ------------------------------------------------------
extern "C" void kernel_launch(void* const* d_in, const int* in_sizes, int n_in,
                              void* d_out, int out_size) {
    const float* x  = (const float*)d_in[0];
    const void*  ei = d_in[1];
    const float *W1 = (const float*)d_in[2],  *b1 = (const float*)d_in[3];
    const float *W2 = (const float*)d_in[4],  *b2 = (const float*)d_in[5];
    const float *W3 = (const float*)d_in[6],  *b3 = (const float*)d_in[7];
    const float *Wl1= (const float*)d_in[8],  *bl1= (const float*)d_in[9];
    const float *Wl2= (const float*)d_in[10], *bl2= (const float*)d_in[11];
    const float *Wl3= (const float*)d_in[12], *bl3= (const float*)d_in[13];
    float* out = (float*)d_out;

    int dev = 0;
    cudaGetDevice(&dev);
    int sms = 0;
    cudaDeviceGetAttribute(&sms, cudaDevAttrMultiProcessorCount, dev);
    int nb = 0;
    cudaOccupancyMaxActiveBlocksPerMultiprocessor(&nb, k_persist, TPB, 0);
    if (nb < 1) nb = 1;
    long long grid = (long long)nb * (sms > 0 ? sms : 1);
    if (grid > 2048) grid = 2048;
    if (grid < 1) grid = 1;

    k_persist<<<(int)grid, TPB>>>(x, ei, W1, b1, W2, b2, W3, b3,
                                  Wl1, bl1, Wl2, bl2, Wl3, bl3, out);
}

// round 6
// speedup vs baseline: 1.3740x; 1.3740x over previous
#include <cuda_runtime.h>
#include <cuda_bf16.h>
#include <stdint.h>

#define N_NODES 50000
#define N_EDGES 800000

// ---------------- scratch (device globals; no allocation allowed) ----------
__device__ int   g_is64;
__device__ int   g_counter;
__device__ int   g_deg[N_NODES];
__device__ int   g_rowptr[N_NODES];     // start of bucket
__device__ int   g_rowcur[N_NODES];     // after scatter: end of bucket
__device__ int   g_colidx[N_EDGES];
__device__ float g_dis[N_NODES];
__device__ float g_feat[N_NODES * 64];
__device__ float g_agg [N_NODES * 64];
__device__ float g_actA[N_NODES * 128];
__device__ float g_actB[N_NODES * 128];

// ---------------- packed f32x2 helpers (Blackwell) ---------------------------
__device__ __forceinline__ unsigned long long pack2(float x, float y) {
    unsigned long long r;
    asm("mov.b64 %0, {%1, %2};" : "=l"(r) : "f"(x), "f"(y));
    return r;
}
__device__ __forceinline__ void unpack2(unsigned long long v, float& x, float& y) {
    asm("mov.b64 {%0, %1}, %2;" : "=f"(x), "=f"(y) : "l"(v));
}
__device__ __forceinline__ unsigned long long fma2(unsigned long long a,
                                                   unsigned long long b,
                                                   unsigned long long c) {
    unsigned long long d;
    asm("fma.rn.f32x2 %0, %1, %2, %3;" : "=l"(d) : "l"(a), "l"(b), "l"(c));
    return d;
}

__device__ __forceinline__ int edge_at(const void* ei, long long idx) {
    if (g_is64) return (int)((const long long*)ei)[idx];
    return ((const int*)ei)[idx];
}

// ---------------- CSR build (scan-free) --------------------------------------
__global__ void k_init(const void* __restrict__ ei) {
    int i = blockIdx.x * blockDim.x + threadIdx.x;
    if (i < N_NODES) g_deg[i] = 0;
    if (i == 0) {
        g_counter = 0;
        const long long* p = (const long long*)ei;
        int ok64 = 1;
        for (int q = 0; q < 64; q++) {
            long long v = p[q];
            if (v < 0 || v >= N_NODES) { ok64 = 0; break; }
        }
        g_is64 = ok64;
    }
}

__global__ void k_hist(const void* __restrict__ ei) {
    int e = blockIdx.x * blockDim.x + threadIdx.x;
    if (e < N_EDGES) {
        int d = edge_at(ei, (long long)N_EDGES + e);
        if (d >= 0 && d < N_NODES) atomicAdd(&g_deg[d], 1);
    }
}

// disjoint bucket bases via atomic bump (order irrelevant for a sum)
__global__ void k_base() {
    int i = blockIdx.x * blockDim.x + threadIdx.x;
    if (i < N_NODES) {
        int d = g_deg[i];
        int base = atomicAdd(&g_counter, d);
        g_rowptr[i] = base;
        g_rowcur[i] = base;
        g_dis[i]    = rsqrtf((float)(d + 1));
    }
}

// scatter edges into buckets + scale layer-1 input features by dis
__global__ void k_scatter(const void* __restrict__ ei,
                          const float4* __restrict__ x, float4* __restrict__ f) {
    int t = blockIdx.x * blockDim.x + threadIdx.x;
    int stride = gridDim.x * blockDim.x;
    for (int e = t; e < N_EDGES; e += stride) {
        int s = edge_at(ei, e);
        int d = edge_at(ei, (long long)N_EDGES + e);
        if (d >= 0 && d < N_NODES && s >= 0 && s < N_NODES) {
            int p = atomicAdd(&g_rowcur[d], 1);
            g_colidx[p] = s;
        }
    }
    for (int i = t; i < N_NODES * 4; i += stride) {
        float dd = g_dis[i >> 2];
        float4 v = __ldg(&x[i]);
        v.x *= dd; v.y *= dd; v.z *= dd; v.w *= dd;
        f[i] = v;
    }
}

// ---------------- aggregation kernels (proven R3 versions) -------------------
// end-of-bucket comes from g_rowcur (post-scatter)

__global__ void k_agg16(const float* __restrict__ g, float* __restrict__ agg) {
    int t = blockIdx.x * blockDim.x + threadIdx.x;
    int node = t >> 4;
    if (node >= N_NODES) return;
    int lane = t & 15;

    float acc = __ldg(&g[node * 16 + lane]);
    int p   = g_rowptr[node];
    int end = g_rowcur[node];
    for (; p + 4 <= end; p += 4) {
        int s0 = g_colidx[p + 0], s1 = g_colidx[p + 1];
        int s2 = g_colidx[p + 2], s3 = g_colidx[p + 3];
        acc += __ldg(&g[s0 * 16 + lane]);
        acc += __ldg(&g[s1 * 16 + lane]);
        acc += __ldg(&g[s2 * 16 + lane]);
        acc += __ldg(&g[s3 * 16 + lane]);
    }
    for (; p < end; p++)
        acc += __ldg(&g[g_colidx[p] * 16 + lane]);

    agg[node * 16 + lane] = acc * g_dis[node];
}

__global__ void k_agg32(const float* __restrict__ g, float* __restrict__ agg) {
    int warp = (blockIdx.x * blockDim.x + threadIdx.x) >> 5;
    if (warp >= N_NODES) return;
    int lane = threadIdx.x & 31;

    float acc = __ldg(&g[warp * 32 + lane]);
    int p   = g_rowptr[warp];
    int end = g_rowcur[warp];
    for (; p + 4 <= end; p += 4) {
        int s0 = g_colidx[p + 0], s1 = g_colidx[p + 1];
        int s2 = g_colidx[p + 2], s3 = g_colidx[p + 3];
        acc += __ldg(&g[s0 * 32 + lane]);
        acc += __ldg(&g[s1 * 32 + lane]);
        acc += __ldg(&g[s2 * 32 + lane]);
        acc += __ldg(&g[s3 * 32 + lane]);
    }
    for (; p < end; p++)
        acc += __ldg(&g[g_colidx[p] * 32 + lane]);

    agg[warp * 32 + lane] = acc * g_dis[warp];
}

__global__ void k_agg64(const float* __restrict__ g, float* __restrict__ agg) {
    int warp = (blockIdx.x * blockDim.x + threadIdx.x) >> 5;
    if (warp >= N_NODES) return;
    int lane = threadIdx.x & 31;

    const float2* g2 = (const float2*)g;
    float2 acc = __ldg(&g2[warp * 32 + lane]);
    int p   = g_rowptr[warp];
    int end = g_rowcur[warp];
    for (; p + 4 <= end; p += 4) {
        int s0 = g_colidx[p + 0], s1 = g_colidx[p + 1];
        int s2 = g_colidx[p + 2], s3 = g_colidx[p + 3];
        float2 v0 = __ldg(&g2[s0 * 32 + lane]);
        float2 v1 = __ldg(&g2[s1 * 32 + lane]);
        float2 v2 = __ldg(&g2[s2 * 32 + lane]);
        float2 v3 = __ldg(&g2[s3 * 32 + lane]);
        acc.x += v0.x + v1.x + v2.x + v3.x;
        acc.y += v0.y + v1.y + v2.y + v3.y;
    }
    for (; p < end; p++) {
        float2 v = __ldg(&g2[g_colidx[p] * 32 + lane]);
        acc.x += v.x; acc.y += v.y;
    }

    float dd = g_dis[warp];
    float2 o; o.x = acc.x * dd; o.y = acc.y * dd;
    ((float2*)agg)[warp * 32 + lane] = o;
}

// ---------------- register-tiled GEMM + bias + relu (+dis) (proven R3) ------
template <int DIN, int DOUT, bool SCALE>
__global__ void __launch_bounds__(256) k_gemm2(
        const float* __restrict__ in,
        const float* __restrict__ W,
        const float* __restrict__ b,
        float* __restrict__ out) {
    constexpr int NB  = 64;
    constexpr int TN  = (DOUT >= 32) ? 8 : 4;
    constexpr int TX  = DOUT / TN;
    constexpr int TY  = 256 / TX;
    constexpr int TM  = NB / TY;
    constexpr int KC  = (DIN * DOUT >= 8192) ? 32 : DIN;
    constexpr int NKC = DIN / KC;
    constexpr int INP = KC + 1;
    constexpr int SWW = DOUT + 2 * (DOUT / 32) + 2;

    __shared__ float inS[NB * INP];
    __shared__ float Ws[KC * SWW];

    const int tid  = threadIdx.x;
    const int tx   = tid % TX;
    const int ty   = tid / TX;
    const int node0 = blockIdx.x * NB;

    float bb[TN];
#pragma unroll
    for (int j = 0; j < TN; j++) bb[j] = __ldg(&b[tx * TN + j]);

    unsigned long long acc[TM][TN / 2];
#pragma unroll
    for (int m = 0; m < TM; m++)
#pragma unroll
        for (int j = 0; j < TN / 2; j++) acc[m][j] = 0ull;

    for (int kc = 0; kc < NKC; kc++) {
        const int k0 = kc * KC;
        for (int i = tid; i < NB * KC; i += 256) {
            int r = i / KC, c = i - r * KC;
            int node = node0 + r;
            inS[r * INP + c] =
                (node < N_NODES) ? __ldg(&in[(size_t)node * DIN + k0 + c]) : 0.f;
        }
        for (int i = tid; i < KC * DOUT; i += 256) {
            int r = i / DOUT, c = i - r * DOUT;
            Ws[r * SWW + c + 2 * (c >> 5)] = __ldg(&W[(size_t)(k0 + r) * DOUT + c]);
        }
        __syncthreads();

#pragma unroll
        for (int k = 0; k < KC; k++) {
            unsigned long long a2[TM];
#pragma unroll
            for (int m = 0; m < TM; m++) {
                float a = inS[(ty * TM + m) * INP + k];
                a2[m] = pack2(a, a);
            }
#pragma unroll
            for (int j = 0; j < TN / 2; j++) {
                int c = tx * TN + 2 * j;
                float2 wv = *reinterpret_cast<const float2*>(
                    &Ws[k * SWW + c + 2 * (c >> 5)]);
                unsigned long long w2 = pack2(wv.x, wv.y);
#pragma unroll
                for (int m = 0; m < TM; m++)
                    acc[m][j] = fma2(a2[m], w2, acc[m][j]);
            }
        }
        if (kc + 1 < NKC) __syncthreads();
    }

#pragma unroll
    for (int m = 0; m < TM; m++) {
        int node = node0 + ty * TM + m;
        if (node >= N_NODES) continue;
        float sc = SCALE ? g_dis[node] : 1.f;
        float vals[TN];
#pragma unroll
        for (int j = 0; j < TN / 2; j++) {
            float v0, v1;
            unpack2(acc[m][j], v0, v1);
            v0 += bb[2 * j];     v1 += bb[2 * j + 1];
            v0 = v0 > 0.f ? v0 : 0.f;
            v1 = v1 > 0.f ? v1 : 0.f;
            vals[2 * j]     = v0 * sc;
            vals[2 * j + 1] = v1 * sc;
        }
        float4* o = (float4*)(out + (size_t)node * DOUT + tx * TN);
#pragma unroll
        for (int q = 0; q < TN / 4; q++)
            o[q] = make_float4(vals[4 * q], vals[4 * q + 1],
                               vals[4 * q + 2], vals[4 * q + 3]);
    }
}

// ---------------- fused dense l2+l3: 64 -> relu32 -> relu16 -----------------
__global__ void __launch_bounds__(256) k_l23(
        const float* __restrict__ in,
        const float* __restrict__ W2, const float* __restrict__ b2,
        const float* __restrict__ W3, const float* __restrict__ b3,
        float* __restrict__ out) {
    __shared__ float h1S[64 * 65];
    __shared__ float h2S[64 * 34];
    __shared__ float W2s[64 * 34];
    __shared__ float W3s[32 * 18];
    __shared__ float b2s[32];
    __shared__ float b3s[16];

    const int tid   = threadIdx.x;
    const int node0 = blockIdx.x * 64;

    for (int i = tid; i < 64 * 64; i += 256) {
        int r = i >> 6, c = i & 63;
        int n = node0 + r;
        h1S[r * 65 + c] = (n < N_NODES) ? __ldg(&in[(size_t)n * 64 + c]) : 0.f;
    }
    for (int i = tid; i < 64 * 32; i += 256) {
        int r = i >> 5, c = i & 31;
        W2s[r * 34 + c] = __ldg(&W2[i]);
    }
    for (int i = tid; i < 32 * 16; i += 256) {
        int r = i >> 4, c = i & 15;
        W3s[r * 18 + c] = __ldg(&W3[i]);
    }
    if (tid < 32) b2s[tid] = __ldg(&b2[tid]);
    else if (tid < 48) b3s[tid - 32] = __ldg(&b3[tid - 32]);
    __syncthreads();

    // h2 = relu(h1 @ W2 + b2): 4 threads/node, 8 outputs each
    {
        int r  = tid >> 2;
        int c0 = (tid & 3) * 8;
        unsigned long long acc[4] = {0ull, 0ull, 0ull, 0ull};
#pragma unroll
        for (int k = 0; k < 64; k++) {
            float a = h1S[r * 65 + k];
            unsigned long long a2 = pack2(a, a);
#pragma unroll
            for (int j = 0; j < 4; j++) {
                float2 wv = *reinterpret_cast<const float2*>(&W2s[k * 34 + c0 + 2 * j]);
                acc[j] = fma2(a2, pack2(wv.x, wv.y), acc[j]);
            }
        }
#pragma unroll
        for (int j = 0; j < 4; j++) {
            float v0, v1;
            unpack2(acc[j], v0, v1);
            v0 += b2s[c0 + 2 * j];     v1 += b2s[c0 + 2 * j + 1];
            h2S[r * 34 + c0 + 2 * j]     = v0 > 0.f ? v0 : 0.f;
            h2S[r * 34 + c0 + 2 * j + 1] = v1 > 0.f ? v1 : 0.f;
        }
    }
    __syncthreads();

    // out = relu(h2 @ W3 + b3): 4 threads/node, 4 outputs each
    {
        int r  = tid >> 2;
        int c0 = (tid & 3) * 4;
        unsigned long long acc[2] = {0ull, 0ull};
#pragma unroll
        for (int k = 0; k < 32; k++) {
            float a = h2S[r * 34 + k];
            unsigned long long a2 = pack2(a, a);
#pragma unroll
            for (int j = 0; j < 2; j++) {
                float2 wv = *reinterpret_cast<const float2*>(&W3s[k * 18 + c0 + 2 * j]);
                acc[j] = fma2(a2, pack2(wv.x, wv.y), acc[j]);
            }
        }
        int n = node0 + r;
        if (n < N_NODES) {
            float v[4];
            unpack2(acc[0], v[0], v[1]);
            unpack2(acc[1], v[2], v[3]);
#pragma unroll
            for (int j = 0; j < 4; j++) {
                v[j] += b3s[c0 + j];
                v[j] = v[j] > 0.f ? v[j] : 0.f;
            }
            *(float4*)(out + (size_t)n * 16 + c0) = make_float4(v[0], v[1], v[2], v[3]);
        }
    }
}

// ---------------- launch ------------------------------------------------------
extern "C" void kernel_launch(void* const* d_in, const int* in_sizes, int n_in,
                              void* d_out, int out_size) {
    const float* x  = (const float*)d_in[0];
    const void*  ei = d_in[1];
    const float *W1 = (const float*)d_in[2],  *b1 = (const float*)d_in[3];
    const float *W2 = (const float*)d_in[4],  *b2 = (const float*)d_in[5];
    const float *W3 = (const float*)d_in[6],  *b3 = (const float*)d_in[7];
    const float *Wl1= (const float*)d_in[8],  *bl1= (const float*)d_in[9];
    const float *Wl2= (const float*)d_in[10], *bl2= (const float*)d_in[11];
    const float *Wl3= (const float*)d_in[12], *bl3= (const float*)d_in[13];
    float* out = (float*)d_out;

    float *feat, *agg, *actA, *actB;
    cudaGetSymbolAddress((void**)&feat, g_feat);
    cudaGetSymbolAddress((void**)&agg,  g_agg);
    cudaGetSymbolAddress((void**)&actA, g_actA);
    cudaGetSymbolAddress((void**)&actB, g_actB);

    const int TB = 256;
    const int nodeBlocks = (N_NODES + TB - 1) / TB;
    const int edgeBlocks = (N_EDGES + TB - 1) / TB;
    const int tileBlocks = (N_NODES + 63) / 64;
    const int hwBlocks   = (N_NODES * 16 + TB - 1) / TB;
    const int wBlocks    = (N_NODES * 32 + TB - 1) / TB;

    // --- CSR build (scan-free: 4 kernels) ---
    k_init<<<nodeBlocks, TB>>>(ei);
    k_hist<<<edgeBlocks, TB>>>(ei);
    k_base<<<nodeBlocks, TB>>>();
    k_scatter<<<edgeBlocks, TB>>>(ei, (const float4*)x, (float4*)feat);

    // --- conv 1: 16 -> 32 ---
    k_agg16<<<hwBlocks, TB>>>(feat, agg);
    k_gemm2<16, 32, true><<<tileBlocks, TB>>>(agg, W1, b1, feat);

    // --- conv 2: 32 -> 64 ---
    k_agg32<<<wBlocks, TB>>>(feat, agg);
    k_gemm2<32, 64, true><<<wBlocks * 0 + tileBlocks, TB>>>(agg, W2, b2, feat);

    // --- conv 3: 64 -> 128 ---
    k_agg64<<<wBlocks, TB>>>(feat, agg);
    k_gemm2<64, 128, false><<<tileBlocks, TB>>>(agg, W3, b3, actA);

    // --- dense layers ---
    k_gemm2<128, 64, false><<<tileBlocks, TB>>>(actA, Wl1, bl1, actB);
    k_l23<<<tileBlocks, TB>>>(actB, Wl2, bl2, Wl3, bl3, out);
}